// round 5
// baseline (speedup 1.0000x reference)
#include <cuda_runtime.h>
#include <cuda_bf16.h>
#include <cstdint>

// ============================ problem constants ============================
#define B_SZ   32
#define S_SZ   4096
#define E_SZ   256
#define A_SZ   256
#define NROWS  (S_SZ * B_SZ)       // 131072 rows, row r = s*32 + b
#define TILE_M 128
#define NTILES (NROWS / TILE_M)    // 1024
#define NCHUNK 32                  // a-columns per chunk
#define NCH    (A_SZ / NCHUNK)     // 8 chunks

// ============================ device scratch ===============================
__device__ uint2 g_whe[A_SZ * E_SZ / 4];   // bf16 hi of We, [a][e] row-major (512B rows)
__device__ uint2 g_wle[A_SZ * E_SZ / 4];   // bf16 lo of We
__device__ float g_proj[B_SZ * A_SZ];      // proj[b][a] = dh[b]·Wd[a] + bias[a]
__device__ float g_scores[NROWS];          // scores[r], r = s*32+b
__device__ float g_norm[NROWS];            // ||eo[s,b,:]||
__device__ float g_smax[B_SZ];
__device__ float g_sinv[B_SZ];
__device__ float g_attpart[B_SZ * 8 * E_SZ];

// ============================ helpers ======================================
__device__ __forceinline__ uint32_t smem_u32(const void* p) {
    uint32_t a;
    asm("{ .reg .u64 t; cvta.to.shared.u64 t, %1; cvt.u32.u64 %0, t; }" : "=r"(a) : "l"(p));
    return a;
}
__device__ __forceinline__ void cp16(uint32_t dst, const void* src) {
    asm volatile("cp.async.cg.shared.global [%0], [%1], 16;" :: "r"(dst), "l"(src));
}
__device__ __forceinline__ void cp_commit() {
    asm volatile("cp.async.commit_group;" ::: "memory");
}
__device__ __forceinline__ void cp_wait0() {
    asm volatile("cp.async.wait_group 0;" ::: "memory");
}
__device__ __forceinline__ void ldsm4(uint32_t (&r)[4], uint32_t addr) {
    asm volatile("ldmatrix.sync.aligned.m8n8.x4.shared.b16 {%0,%1,%2,%3}, [%4];"
                 : "=r"(r[0]), "=r"(r[1]), "=r"(r[2]), "=r"(r[3]) : "r"(addr));
}
__device__ __forceinline__ void mma16816(float (&c)[4], const uint32_t (&a)[4],
                                         uint32_t b0, uint32_t b1) {
    asm volatile(
        "mma.sync.aligned.m16n8k16.row.col.f32.bf16.bf16.f32 "
        "{%0,%1,%2,%3}, {%4,%5,%6,%7}, {%8,%9}, {%0,%1,%2,%3};"
        : "+f"(c[0]), "+f"(c[1]), "+f"(c[2]), "+f"(c[3])
        : "r"(a[0]), "r"(a[1]), "r"(a[2]), "r"(a[3]), "r"(b0), "r"(b1));
}
// fast accurate tanh: 2 MUFU (EX2 + RCP), abs err ~1e-6
__device__ __forceinline__ float tanh_fast(float x) {
    float xc = fminf(fmaxf(x, -15.f), 15.f);
    float u  = __expf(xc + xc);
    return __fdividef(u - 1.f, u + 1.f);
}
__device__ __forceinline__ uint32_t packbf2(__nv_bfloat16 a, __nv_bfloat16 b) {
    return (uint32_t)__bfloat16_as_ushort(a) | ((uint32_t)__bfloat16_as_ushort(b) << 16);
}

// ============================ kernel 1: split We ===========================
__global__ void splitw_kernel(const float* __restrict__ W) {
    int i = blockIdx.x * 256 + threadIdx.x;     // 65536 = A*E
    int a = i >> 8, e = i & 255;
    float w = W[a * 512 + 256 + e];             // We = W[:, 256:512]
    __nv_bfloat16 h = __float2bfloat16(w);
    float lo = w - __bfloat162float(h);
    ((__nv_bfloat16*)g_whe)[i] = h;
    ((__nv_bfloat16*)g_wle)[i] = __float2bfloat16(lo);
}

// ============================ kernel 2: proj ===============================
__global__ void proj_kernel(const float* __restrict__ dh, const float* __restrict__ W,
                            const float* __restrict__ bias) {
    int b = blockIdx.x, a = threadIdx.x;
    __shared__ float dsh[256];
    dsh[a] = dh[b * 256 + a];
    __syncthreads();
    const float4* wr = (const float4*)(W + a * 512);   // Wd row of thread's a
    float acc = bias[a];
#pragma unroll 8
    for (int d4 = 0; d4 < 64; d4++) {
        float4 w = wr[d4];
        acc += w.x * dsh[d4 * 4 + 0] + w.y * dsh[d4 * 4 + 1]
             + w.z * dsh[d4 * 4 + 2] + w.w * dsh[d4 * 4 + 3];
    }
    g_proj[b * 256 + a] = acc;
}

// ========== kernel 3: fused GEMM (HMMA bf16 3-split) + tanh + rowsum =======
// smem: A_hi [128][256]bf16 (512B rows, 16B-chunk XOR swizzle), A_lo same,
//       We chunk hi/lo [32][256]bf16, proj padded, nsq partials.
#define OFF_AH   0
#define OFF_AL   65536
#define OFF_WH   131072
#define OFF_WL   147456
#define OFF_PROJ 163840                 // 32 rows x 260 floats
#define OFF_NSQ  (OFF_PROJ + 32 * 260 * 4)   // 197120: 128 x 2 floats
#define SMEM_P1  (OFF_NSQ + 1024)       // 198144 bytes

__global__ void __launch_bounds__(256, 1) phase1_kernel(const float* __restrict__ eo) {
    extern __shared__ char smem[];
    const uint32_t sb  = smem_u32(smem);
    const int tid  = threadIdx.x;
    const int lane = tid & 31;
    const int w    = tid >> 5;
    const int r0   = blockIdx.x * TILE_M;

    float* proj_s = (float*)(smem + OFF_PROJ);
    float* nsq2   = (float*)(smem + OFF_NSQ);

    // ---- prefetch We chunk 0 (L2-resident) via cp.async
    {
#pragma unroll
        for (int it = 0; it < 4; it++) {
            int idx = it * 256 + tid;           // 0..1023
            int n = idx >> 5, ck = idx & 31;
            uint32_t dst = (uint32_t)(n * 512 + ((ck ^ (n & 7)) << 4));
            cp16(sb + OFF_WH + dst, g_whe + n * 64 + ck * 2);
            cp16(sb + OFF_WL + dst, g_wle + n * 64 + ck * 2);
        }
        cp_commit();
    }

    // ---- load eo tile (128 x 256 f32), convert to bf16 hi/lo, sum squares
    {
        const float4* xg = (const float4*)eo;
        float ssq_acc;  // per-iteration
#pragma unroll 4
        for (int it = 0; it < 32; it++) {
            int idx = it * 256 + tid;
            int m = idx >> 6, k4 = idx & 63;    // all lanes in warp share m
            float4 v = xg[(size_t)(r0 + m) * 64 + k4];
            __nv_bfloat16 h0 = __float2bfloat16(v.x);
            __nv_bfloat16 h1 = __float2bfloat16(v.y);
            __nv_bfloat16 h2 = __float2bfloat16(v.z);
            __nv_bfloat16 h3 = __float2bfloat16(v.w);
            uint32_t off = (uint32_t)(m * 512 + (((k4 >> 1) ^ (m & 7)) << 4) + ((k4 & 1) << 3));
            *(uint2*)(smem + OFF_AH + off) = make_uint2(packbf2(h0, h1), packbf2(h2, h3));
            float l0 = v.x - __bfloat162float(h0);
            float l1 = v.y - __bfloat162float(h1);
            float l2 = v.z - __bfloat162float(h2);
            float l3 = v.w - __bfloat162float(h3);
            *(uint2*)(smem + OFF_AL + off) = make_uint2(
                packbf2(__float2bfloat16(l0), __float2bfloat16(l1)),
                packbf2(__float2bfloat16(l2), __float2bfloat16(l3)));
            ssq_acc = v.x * v.x + v.y * v.y + v.z * v.z + v.w * v.w;
#pragma unroll
            for (int o = 16; o; o >>= 1)
                ssq_acc += __shfl_xor_sync(0xffffffffu, ssq_acc, o);
            if (lane == 0) nsq2[m * 2 + (w & 1)] = ssq_acc;   // half-row partial
        }
    }
    // ---- stage proj into padded smem (stride 260 floats)
    {
        const float4* pg = (const float4*)g_proj;
#pragma unroll
        for (int it = 0; it < 8; it++) {
            int idx = it * 256 + tid;           // 0..2047 float4s
            int b = idx >> 6, q = (idx & 63) * 4;
            float4 v = pg[idx];
            *(float4*)(proj_s + b * 260 + q) = v;
        }
    }
    __syncthreads();

    // norms (conversion partials now visible)
    if (tid < 128) {
        g_norm[r0 + tid] = sqrtf(nsq2[tid * 2] + nsq2[tid * 2 + 1]);
    }

    // ---- per-warp fragment lane constants
    const int m0 = w * 16;
    const int t  = lane >> 3, rin = lane & 7;
    // A ldmatrix: tiles (m0..+7,k0-7),(m0+8..15,k0-7),(m0..+7,k8-15),(m0+8..+15,k8-15)
    const int a_m     = m0 + ((t & 1) << 3) + rin;
    const int a_khalf = t >> 1;
    const uint32_t a_base_h = sb + OFF_AH + (uint32_t)(a_m * 512);
    const uint32_t a_base_l = sb + OFF_AL + (uint32_t)(a_m * 512);
    const int a_sw = a_m & 7;
    // B ldmatrix (per 16-n group): tiles (n0-7,k0-7),(n0-7,k8-15),(n8-15,k0-7),(n8-15,k8-15)
    const int b_n     = ((t >> 1) << 3) + rin;   // 0..15
    const int b_khalf = t & 1;
    const int b_sw    = b_n & 7;                 // (b_n+16)&7 == b_n&7

    const int rlo = m0 + (lane >> 2);     // output row of c[ ][0..1]
    const int qn  = (lane & 3) * 2;       // output col offset within 8-tile
    const float* prow_lo = proj_s + (rlo & 31) * 260;
    const float* prow_hi = proj_s + ((rlo + 8) & 31) * 260;

    float sum_lo = 0.f, sum_hi = 0.f;

    for (int c = 0; c < NCH; c++) {
        cp_wait0();
        __syncthreads();                  // We chunk c visible to everyone

        float acc[4][4];
#pragma unroll
        for (int j = 0; j < 4; j++)
#pragma unroll
            for (int q = 0; q < 4; q++) acc[j][q] = 0.f;

#pragma unroll 4
        for (int ks = 0; ks < 16; ks++) {
            int ck = ks * 2;
            uint32_t ahs[4], als[4], bh0[4], bh1[4], bl0[4], bl1[4];
            uint32_t a_off = (uint32_t)(((ck + a_khalf) ^ a_sw) << 4);
            ldsm4(ahs, a_base_h + a_off);
            ldsm4(als, a_base_l + a_off);
            uint32_t b_off0 = (uint32_t)(b_n * 512 + (((ck + b_khalf) ^ b_sw) << 4));
            uint32_t b_off1 = b_off0 + 16 * 512;
            ldsm4(bh0, sb + OFF_WH + b_off0);
            ldsm4(bh1, sb + OFF_WH + b_off1);
            ldsm4(bl0, sb + OFF_WL + b_off0);
            ldsm4(bl1, sb + OFF_WL + b_off1);
            // hi*hi
            mma16816(acc[0], ahs, bh0[0], bh0[1]);
            mma16816(acc[1], ahs, bh0[2], bh0[3]);
            mma16816(acc[2], ahs, bh1[0], bh1[1]);
            mma16816(acc[3], ahs, bh1[2], bh1[3]);
            // hi*lo
            mma16816(acc[0], ahs, bl0[0], bl0[1]);
            mma16816(acc[1], ahs, bl0[2], bl0[3]);
            mma16816(acc[2], ahs, bl1[0], bl1[1]);
            mma16816(acc[3], ahs, bl1[2], bl1[3]);
            // lo*hi
            mma16816(acc[0], als, bh0[0], bh0[1]);
            mma16816(acc[1], als, bh0[2], bh0[3]);
            mma16816(acc[2], als, bh1[0], bh1[1]);
            mma16816(acc[3], als, bh1[2], bh1[3]);
        }
        __syncthreads();                  // all warps done reading We chunk c

        // prefetch next chunk (overlaps with tanh epilogue below)
        if (c < NCH - 1) {
            int a0 = (c + 1) * NCHUNK;
#pragma unroll
            for (int it = 0; it < 4; it++) {
                int idx = it * 256 + tid;
                int n = idx >> 5, ck2 = idx & 31;
                uint32_t dst = (uint32_t)(n * 512 + ((ck2 ^ (n & 7)) << 4));
                cp16(sb + OFF_WH + dst, g_whe + (a0 + n) * 64 + ck2 * 2);
                cp16(sb + OFF_WL + dst, g_wle + (a0 + n) * 64 + ck2 * 2);
            }
            cp_commit();
        }

        // ---- tanh epilogue for this chunk (32 a-columns)
#pragma unroll
        for (int j = 0; j < 4; j++) {
            int nb = c * NCHUNK + j * 8 + qn;
            float2 pl = *(const float2*)(prow_lo + nb);
            float2 ph = *(const float2*)(prow_hi + nb);
            sum_lo += tanh_fast(acc[j][0] + pl.x) + tanh_fast(acc[j][1] + pl.y);
            sum_hi += tanh_fast(acc[j][2] + ph.x) + tanh_fast(acc[j][3] + ph.y);
        }
    }

    // ---- reduce 4 lanes per row, write scores
    sum_lo += __shfl_xor_sync(0xffffffffu, sum_lo, 1);
    sum_lo += __shfl_xor_sync(0xffffffffu, sum_lo, 2);
    sum_hi += __shfl_xor_sync(0xffffffffu, sum_hi, 1);
    sum_hi += __shfl_xor_sync(0xffffffffu, sum_hi, 2);
    if ((lane & 3) == 0) {
        g_scores[r0 + rlo]     = sum_lo;
        g_scores[r0 + rlo + 8] = sum_hi;
    }
}

// ============================ kernel 4: softmax stats ======================
__global__ void stats_kernel() {
    int b = blockIdx.x, t = threadIdx.x;
    __shared__ float red[256];
    float m = -1e30f;
    for (int s = t; s < S_SZ; s += 256) m = fmaxf(m, g_scores[s * B_SZ + b]);
    red[t] = m; __syncthreads();
    for (int o = 128; o; o >>= 1) { if (t < o) red[t] = fmaxf(red[t], red[t + o]); __syncthreads(); }
    float smax = red[0]; __syncthreads();
    float sum = 0.f;
    for (int s = t; s < S_SZ; s += 256) sum += __expf(g_scores[s * B_SZ + b] - smax);
    red[t] = sum; __syncthreads();
    for (int o = 128; o; o >>= 1) { if (t < o) red[t] += red[t + o]; __syncthreads(); }
    if (t == 0) { g_smax[b] = smax; g_sinv[b] = 1.f / red[0]; }
}

// ======= kernel 5: weights, attn_map, attended partial sums ================
__global__ void attn_kernel(const float* __restrict__ eo, float* __restrict__ out) {
    int sc = blockIdx.x, b = blockIdx.y, t = threadIdx.x;
    __shared__ float wsm[512];
    float smax = g_smax[b], sinv = g_sinv[b];
    int s0 = sc * 512;
#pragma unroll
    for (int i = 0; i < 2; i++) {
        int s = s0 + t + i * 256;
        float wgt = __expf(g_scores[s * B_SZ + b] - smax) * sinv;
        wsm[t + i * 256] = wgt;
        out[8192 + b * S_SZ + s] = wgt * g_norm[s * B_SZ + b];   // attn_map[b][s]
    }
    __syncthreads();
    const float* base = eo + (size_t)s0 * (B_SZ * E_SZ) + b * E_SZ + t;
    float acc = 0.f;
#pragma unroll 8
    for (int s = 0; s < 512; s++)
        acc = fmaf(wsm[s], base[(size_t)s * (B_SZ * E_SZ)], acc);
    g_attpart[(b * 8 + sc) * E_SZ + t] = acc;
}

// ============================ kernel 6: final reduce =======================
__global__ void reduce_kernel(float* __restrict__ out) {
    int b = blockIdx.x, t = threadIdx.x;
    float a = 0.f;
#pragma unroll
    for (int sc = 0; sc < 8; sc++) a += g_attpart[(b * 8 + sc) * E_SZ + t];
    out[b * E_SZ + t] = a;   // attended[b][e]
}

// ============================ launcher =====================================
extern "C" void kernel_launch(void* const* d_in, const int* in_sizes, int n_in,
                              void* d_out, int out_size) {
    const float* dh   = (const float*)d_in[0];  // (1,B,D)
    const float* eo   = (const float*)d_in[1];  // (S,B,E)
    const float* W    = (const float*)d_in[2];  // (A, D+E)
    const float* bias = (const float*)d_in[3];  // (A,)
    float* out = (float*)d_out;                 // [attended(32x256) | attn_map(32x4096)]

    static bool attr_set = false;
    if (!attr_set) {
        cudaFuncSetAttribute(phase1_kernel, cudaFuncAttributeMaxDynamicSharedMemorySize, SMEM_P1);
        attr_set = true;
    }

    splitw_kernel<<<256, 256>>>(W);
    proj_kernel<<<32, 256>>>(dh, W, bias);
    phase1_kernel<<<NTILES, 256, SMEM_P1>>>(eo);
    stats_kernel<<<32, 256>>>();
    attn_kernel<<<dim3(8, 32), 256>>>(eo, out);
    reduce_kernel<<<32, 256>>>(out);
}

// round 9
// speedup vs baseline: 1.0278x; 1.0278x over previous
#include <cuda_runtime.h>
#include <cuda_bf16.h>
#include <cstdint>

// ============================ problem constants ============================
#define B_SZ   32
#define S_SZ   4096
#define E_SZ   256
#define A_SZ   256
#define NROWS  (S_SZ * B_SZ)       // 131072 rows, row r = s*32 + b
#define TILE_M 128
#define NTILES (NROWS / TILE_M)    // 1024
#define NCHUNK 32                  // a-columns per chunk
#define NCH    (A_SZ / NCHUNK)     // 8 chunks
#define NSC    16                  // attn s-chunks

// ============================ device scratch ===============================
__device__ uint2 g_whe[A_SZ * E_SZ / 4];   // bf16 hi of We, [a][e] row-major (512B rows)
__device__ uint2 g_wle[A_SZ * E_SZ / 4];   // bf16 lo of We
__device__ float g_proj[B_SZ * A_SZ];      // proj[b][a]
__device__ float g_scoresT[B_SZ * S_SZ];   // scores[b][s]  (transposed!)
__device__ float g_normT[B_SZ * S_SZ];     // ||eo[s,b,:]|| as [b][s]
__device__ float g_smax[B_SZ];
__device__ float g_sinv[B_SZ];
__device__ float g_attpart[B_SZ * NSC * E_SZ];

// ============================ helpers ======================================
__device__ __forceinline__ uint32_t smem_u32(const void* p) {
    uint32_t a;
    asm("{ .reg .u64 t; cvta.to.shared.u64 t, %1; cvt.u32.u64 %0, t; }" : "=r"(a) : "l"(p));
    return a;
}
__device__ __forceinline__ void cp16(uint32_t dst, const void* src) {
    asm volatile("cp.async.cg.shared.global [%0], [%1], 16;" :: "r"(dst), "l"(src));
}
__device__ __forceinline__ void cp_commit() {
    asm volatile("cp.async.commit_group;" ::: "memory");
}
__device__ __forceinline__ void cp_wait0() {
    asm volatile("cp.async.wait_group 0;" ::: "memory");
}
__device__ __forceinline__ void cp_wait1() {
    asm volatile("cp.async.wait_group 1;" ::: "memory");
}
__device__ __forceinline__ void ldsm4(uint32_t (&r)[4], uint32_t addr) {
    asm volatile("ldmatrix.sync.aligned.m8n8.x4.shared.b16 {%0,%1,%2,%3}, [%4];"
                 : "=r"(r[0]), "=r"(r[1]), "=r"(r[2]), "=r"(r[3]) : "r"(addr));
}
__device__ __forceinline__ void mma16816(float (&c)[4], const uint32_t (&a)[4],
                                         uint32_t b0, uint32_t b1) {
    asm volatile(
        "mma.sync.aligned.m16n8k16.row.col.f32.bf16.bf16.f32 "
        "{%0,%1,%2,%3}, {%4,%5,%6,%7}, {%8,%9}, {%0,%1,%2,%3};"
        : "+f"(c[0]), "+f"(c[1]), "+f"(c[2]), "+f"(c[3])
        : "r"(a[0]), "r"(a[1]), "r"(a[2]), "r"(a[3]), "r"(b0), "r"(b1));
}
// fast accurate tanh: 2 MUFU (EX2 + RCP), abs err ~1e-6
__device__ __forceinline__ float tanh_fast(float x) {
    float xc = fminf(fmaxf(x, -15.f), 15.f);
    float u  = __expf(xc + xc);
    return __fdividef(u - 1.f, u + 1.f);
}
__device__ __forceinline__ uint32_t packbf2f(float a, float b) {
    __nv_bfloat162 h = __float22bfloat162_rn(make_float2(a, b));
    return *(uint32_t*)&h;
}

// ============================ kernel 1: split We ===========================
__global__ void splitw_kernel(const float* __restrict__ W) {
    int i = blockIdx.x * 256 + threadIdx.x;     // 65536 = A*E
    int a = i >> 8, e = i & 255;
    float w = W[a * 512 + 256 + e];             // We = W[:, 256:512]
    __nv_bfloat16 h = __float2bfloat16(w);
    float lo = w - __bfloat162float(h);
    ((__nv_bfloat16*)g_whe)[i] = h;
    ((__nv_bfloat16*)g_wle)[i] = __float2bfloat16(lo);
}

// ============================ kernel 2: proj ===============================
__global__ void proj_kernel(const float* __restrict__ dh, const float* __restrict__ W,
                            const float* __restrict__ bias) {
    int b = blockIdx.x, a = threadIdx.x;
    __shared__ float dsh[256];
    dsh[a] = dh[b * 256 + a];
    __syncthreads();
    const float4* wr = (const float4*)(W + a * 512);   // Wd row of thread's a
    float acc = bias[a];
#pragma unroll 8
    for (int d4 = 0; d4 < 64; d4++) {
        float4 w = wr[d4];
        acc += w.x * dsh[d4 * 4 + 0] + w.y * dsh[d4 * 4 + 1]
             + w.z * dsh[d4 * 4 + 2] + w.w * dsh[d4 * 4 + 3];
    }
    g_proj[b * 256 + a] = acc;
}

// ========== kernel 3: fused GEMM (HMMA bf16 3-split) + tanh + rowsum =======
// smem: A_hi [128][256]bf16 (512B rows, 16B-chunk XOR swizzle), A_lo same,
//       We chunk double-buffered (2 x (16KB hi + 16KB lo)), nsq partials.
#define OFF_AH   0
#define OFF_AL   65536
#define OFF_W    131072                        // W_BUF(b) = OFF_W + b*32768
#define OFF_NSQ  196608                        // 128 x 65 floats
#define SMEM_P1  (OFF_NSQ + 128 * 65 * 4)      // 229888 bytes

__device__ __forceinline__ void prefetch_w(uint32_t sb, int chunk, int tid) {
    const uint32_t wb = (uint32_t)(OFF_W + (chunk & 1) * 32768);
    const int a0 = chunk * NCHUNK;
#pragma unroll
    for (int it = 0; it < 4; it++) {
        int idx = it * 256 + tid;               // 0..1023
        int n = idx >> 5, ck = idx & 31;
        uint32_t dst = (uint32_t)(n * 512 + ((ck ^ (n & 7)) << 4));
        cp16(sb + wb + dst,         g_whe + (a0 + n) * 64 + ck * 2);
        cp16(sb + wb + 16384 + dst, g_wle + (a0 + n) * 64 + ck * 2);
    }
    cp_commit();
}

__global__ void __launch_bounds__(256, 1) phase1_kernel(const float* __restrict__ eo) {
    extern __shared__ char smem[];
    const uint32_t sb  = smem_u32(smem);
    const int tid  = threadIdx.x;
    const int lane = tid & 31;
    const int w    = tid >> 5;
    const int r0   = blockIdx.x * TILE_M;

    float* nsq_part = (float*)(smem + OFF_NSQ);   // [128][65]

    // ---- prefetch We chunks 0 and 1 (L2-resident), two cp.async groups
    prefetch_w(sb, 0, tid);
    prefetch_w(sb, 1, tid);

    // ---- load eo tile (128 x 256 f32) -> bf16 hi/lo (swizzled), ssq partials
    {
        const float4* xg = (const float4*)eo;
        const int k4 = tid & 63;
        const int mb = tid >> 6;
#pragma unroll 4
        for (int it = 0; it < 32; it++) {
            int m = it * 4 + mb;
            float4 v = xg[(size_t)(r0 + m) * 64 + k4];
            uint32_t ph0 = packbf2f(v.x, v.y);
            uint32_t ph1 = packbf2f(v.z, v.w);
            uint32_t off = (uint32_t)(m * 512 + (((k4 >> 1) ^ (m & 7)) << 4) + ((k4 & 1) << 3));
            *(uint2*)(smem + OFF_AH + off) = make_uint2(ph0, ph1);
            // lo residuals via bit-shift bf16->f32
            float l0 = v.x - __uint_as_float(ph0 << 16);
            float l1 = v.y - __uint_as_float(ph0 & 0xffff0000u);
            float l2 = v.z - __uint_as_float(ph1 << 16);
            float l3 = v.w - __uint_as_float(ph1 & 0xffff0000u);
            *(uint2*)(smem + OFF_AL + off) = make_uint2(packbf2f(l0, l1), packbf2f(l2, l3));
            nsq_part[m * 65 + k4] = v.x * v.x + v.y * v.y + v.z * v.z + v.w * v.w;
        }
    }
    __syncthreads();

    // ---- norms: thread m sums 64 partials (conflict-free: stride 65)
    if (tid < 128) {
        const float* p = nsq_part + tid * 65;
        float s = 0.f;
#pragma unroll
        for (int i = 0; i < 64; i++) s += p[i];
        int r = r0 + tid;
        g_normT[(r & 31) * S_SZ + (r >> 5)] = sqrtf(s);
    }

    // ---- per-warp fragment lane constants
    const int m0 = w * 16;
    const int t  = lane >> 3, rin = lane & 7;
    const int a_m     = m0 + ((t & 1) << 3) + rin;
    const int a_khalf = t >> 1;
    const uint32_t a_base_h = sb + OFF_AH + (uint32_t)(a_m * 512);
    const uint32_t a_base_l = sb + OFF_AL + (uint32_t)(a_m * 512);
    const int a_sw = a_m & 7;
    const int b_n     = ((t >> 1) << 3) + rin;   // 0..15
    const int b_khalf = t & 1;
    const int b_sw    = b_n & 7;

    const int rlo = m0 + (lane >> 2);            // output row of c[ ][0..1]
    const int qn  = (lane & 3) * 2;
    const float2* pl_base = (const float2*)(g_proj + (rlo & 31) * 256);
    const float2* ph_base = (const float2*)(g_proj + ((rlo + 8) & 31) * 256);

    float sum_lo = 0.f, sum_hi = 0.f;

    for (int c = 0; c < NCH; c++) {
        if (c == NCH - 1) cp_wait0(); else cp_wait1();
        __syncthreads();                  // We chunk c visible to everyone

        const uint32_t base_wh = sb + (uint32_t)(OFF_W + (c & 1) * 32768);
        const uint32_t base_wl = base_wh + 16384;

        float acc[4][4];
#pragma unroll
        for (int j = 0; j < 4; j++)
#pragma unroll
            for (int q = 0; q < 4; q++) acc[j][q] = 0.f;

#pragma unroll 4
        for (int ks = 0; ks < 16; ks++) {
            int ck = ks * 2;
            uint32_t ahs[4], als[4], bh0[4], bh1[4], bl0[4], bl1[4];
            uint32_t a_off = (uint32_t)(((ck + a_khalf) ^ a_sw) << 4);
            ldsm4(ahs, a_base_h + a_off);
            ldsm4(als, a_base_l + a_off);
            uint32_t b_off0 = (uint32_t)(b_n * 512 + (((ck + b_khalf) ^ b_sw) << 4));
            uint32_t b_off1 = b_off0 + 16 * 512;
            ldsm4(bh0, base_wh + b_off0);
            ldsm4(bh1, base_wh + b_off1);
            ldsm4(bl0, base_wl + b_off0);
            ldsm4(bl1, base_wl + b_off1);
            // hi*hi
            mma16816(acc[0], ahs, bh0[0], bh0[1]);
            mma16816(acc[1], ahs, bh0[2], bh0[3]);
            mma16816(acc[2], ahs, bh1[0], bh1[1]);
            mma16816(acc[3], ahs, bh1[2], bh1[3]);
            // hi*lo
            mma16816(acc[0], ahs, bl0[0], bl0[1]);
            mma16816(acc[1], ahs, bl0[2], bl0[3]);
            mma16816(acc[2], ahs, bl1[0], bl1[1]);
            mma16816(acc[3], ahs, bl1[2], bl1[3]);
            // lo*hi
            mma16816(acc[0], als, bh0[0], bh0[1]);
            mma16816(acc[1], als, bh0[2], bh0[3]);
            mma16816(acc[2], als, bh1[0], bh1[1]);
            mma16816(acc[3], als, bh1[2], bh1[3]);
        }
        __syncthreads();                  // all warps done reading We buf (c&1)

        // prefetch chunk c+2 into the buffer just freed (overlaps epilogue + next MMA)
        if (c + 2 < NCH) prefetch_w(sb, c + 2, tid);

        // ---- tanh epilogue for this chunk (32 a-columns); proj from gmem (L1)
#pragma unroll
        for (int j = 0; j < 4; j++) {
            int nb2 = (c * NCHUNK + j * 8 + qn) >> 1;   // float2 index
            float2 pl = __ldg(pl_base + nb2);
            float2 ph = __ldg(ph_base + nb2);
            sum_lo += tanh_fast(acc[j][0] + pl.x) + tanh_fast(acc[j][1] + pl.y);
            sum_hi += tanh_fast(acc[j][2] + ph.x) + tanh_fast(acc[j][3] + ph.y);
        }
    }

    // ---- reduce 4 lanes per row, write transposed scores
    sum_lo += __shfl_xor_sync(0xffffffffu, sum_lo, 1);
    sum_lo += __shfl_xor_sync(0xffffffffu, sum_lo, 2);
    sum_hi += __shfl_xor_sync(0xffffffffu, sum_hi, 1);
    sum_hi += __shfl_xor_sync(0xffffffffu, sum_hi, 2);
    if ((lane & 3) == 0) {
        int r = r0 + rlo;
        g_scoresT[(r & 31) * S_SZ + (r >> 5)] = sum_lo;
        r += 8;
        g_scoresT[(r & 31) * S_SZ + (r >> 5)] = sum_hi;
    }
}

// ============================ kernel 4: softmax stats ======================
__global__ void stats_kernel() {
    int b = blockIdx.x, t = threadIdx.x;
    __shared__ float red[256];
    const float* sc = g_scoresT + b * S_SZ;
    float m = -1e30f;
#pragma unroll 4
    for (int s = t; s < S_SZ; s += 256) m = fmaxf(m, sc[s]);
    red[t] = m; __syncthreads();
    for (int o = 128; o; o >>= 1) { if (t < o) red[t] = fmaxf(red[t], red[t + o]); __syncthreads(); }
    float smax = red[0]; __syncthreads();
    float sum = 0.f;
#pragma unroll 4
    for (int s = t; s < S_SZ; s += 256) sum += __expf(sc[s] - smax);
    red[t] = sum; __syncthreads();
    for (int o = 128; o; o >>= 1) { if (t < o) red[t] += red[t + o]; __syncthreads(); }
    if (t == 0) { g_smax[b] = smax; g_sinv[b] = 1.f / red[0]; }
}

// ======= kernel 5: weights, attn_map, attended partial sums ================
__global__ void attn_kernel(const float* __restrict__ eo, float* __restrict__ out) {
    int sc = blockIdx.x, b = blockIdx.y, t = threadIdx.x;
    __shared__ float wsm[256];
    float smax = g_smax[b], sinv = g_sinv[b];
    int s0 = sc * 256;
    int s = s0 + t;
    float wgt = __expf(g_scoresT[b * S_SZ + s] - smax) * sinv;
    wsm[t] = wgt;
    out[8192 + b * S_SZ + s] = wgt * g_normT[b * S_SZ + s];   // attn_map[b][s]
    __syncthreads();
    const float* base = eo + (size_t)s0 * (B_SZ * E_SZ) + b * E_SZ + t;
    float acc = 0.f;
#pragma unroll 16
    for (int s2 = 0; s2 < 256; s2++)
        acc = fmaf(wsm[s2], base[(size_t)s2 * (B_SZ * E_SZ)], acc);
    g_attpart[(b * NSC + sc) * E_SZ + t] = acc;
}

// ============================ kernel 6: final reduce =======================
__global__ void reduce_kernel(float* __restrict__ out) {
    int b = blockIdx.x, t = threadIdx.x;
    float a = 0.f;
#pragma unroll
    for (int sc = 0; sc < NSC; sc++) a += g_attpart[(b * NSC + sc) * E_SZ + t];
    out[b * E_SZ + t] = a;   // attended[b][e]
}

// ============================ launcher =====================================
extern "C" void kernel_launch(void* const* d_in, const int* in_sizes, int n_in,
                              void* d_out, int out_size) {
    const float* dh   = (const float*)d_in[0];  // (1,B,D)
    const float* eo   = (const float*)d_in[1];  // (S,B,E)
    const float* W    = (const float*)d_in[2];  // (A, D+E)
    const float* bias = (const float*)d_in[3];  // (A,)
    float* out = (float*)d_out;                 // [attended(32x256) | attn_map(32x4096)]

    cudaFuncSetAttribute(phase1_kernel, cudaFuncAttributeMaxDynamicSharedMemorySize, SMEM_P1);

    splitw_kernel<<<256, 256>>>(W);
    proj_kernel<<<32, 256>>>(dh, W, bias);
    phase1_kernel<<<NTILES, 256, SMEM_P1>>>(eo);
    stats_kernel<<<32, 256>>>();
    attn_kernel<<<dim3(NSC, 32), 256>>>(eo, out);
    reduce_kernel<<<32, 256>>>(out);
}

// round 10
// speedup vs baseline: 1.0932x; 1.0637x over previous
#include <cuda_runtime.h>
#include <cuda_bf16.h>
#include <cstdint>

// ============================ problem constants ============================
#define B_SZ   32
#define S_SZ   4096
#define E_SZ   256
#define A_SZ   256
#define NROWS  (S_SZ * B_SZ)       // 131072 rows, row r = s*32 + b
#define TILE_M 64
#define NTILES (NROWS / TILE_M)    // 2048
#define NCHUNK 32                  // a-columns per chunk
#define NCH    (A_SZ / NCHUNK)     // 8 chunks
#define NSC    16                  // attn s-chunks

// ============================ device scratch ===============================
__device__ uint2 g_whe[A_SZ * E_SZ / 4];   // bf16 hi of We, [a][e] row-major (512B rows)
__device__ uint2 g_wle[A_SZ * E_SZ / 4];   // bf16 lo of We
__device__ float g_proj[B_SZ * A_SZ];      // proj[b][a]
__device__ float g_scoresT[B_SZ * S_SZ];   // scores[b][s]  (transposed)
__device__ float g_normT[B_SZ * S_SZ];     // ||eo[s,b,:]|| as [b][s]
__device__ float g_smax[B_SZ];
__device__ float g_sinv[B_SZ];
__device__ float g_attpart[B_SZ * NSC * E_SZ];

// ============================ helpers ======================================
__device__ __forceinline__ uint32_t smem_u32(const void* p) {
    uint32_t a;
    asm("{ .reg .u64 t; cvta.to.shared.u64 t, %1; cvt.u32.u64 %0, t; }" : "=r"(a) : "l"(p));
    return a;
}
__device__ __forceinline__ void cp16(uint32_t dst, const void* src) {
    asm volatile("cp.async.cg.shared.global [%0], [%1], 16;" :: "r"(dst), "l"(src));
}
__device__ __forceinline__ void cp_commit() {
    asm volatile("cp.async.commit_group;" ::: "memory");
}
__device__ __forceinline__ void cp_wait0() {
    asm volatile("cp.async.wait_group 0;" ::: "memory");
}
__device__ __forceinline__ void ldsm4(uint32_t (&r)[4], uint32_t addr) {
    asm volatile("ldmatrix.sync.aligned.m8n8.x4.shared.b16 {%0,%1,%2,%3}, [%4];"
                 : "=r"(r[0]), "=r"(r[1]), "=r"(r[2]), "=r"(r[3]) : "r"(addr));
}
__device__ __forceinline__ void mma16816(float (&c)[4], const uint32_t (&a)[4],
                                         uint32_t b0, uint32_t b1) {
    asm volatile(
        "mma.sync.aligned.m16n8k16.row.col.f32.bf16.bf16.f32 "
        "{%0,%1,%2,%3}, {%4,%5,%6,%7}, {%8,%9}, {%0,%1,%2,%3};"
        : "+f"(c[0]), "+f"(c[1]), "+f"(c[2]), "+f"(c[3])
        : "r"(a[0]), "r"(a[1]), "r"(a[2]), "r"(a[3]), "r"(b0), "r"(b1));
}
// fast accurate tanh: 2 MUFU (EX2 + RCP), abs err ~1e-6
__device__ __forceinline__ float tanh_fast(float x) {
    float xc = fminf(fmaxf(x, -15.f), 15.f);
    float u  = __expf(xc + xc);
    return __fdividef(u - 1.f, u + 1.f);
}
__device__ __forceinline__ uint32_t packbf2f(float a, float b) {
    __nv_bfloat162 h = __float22bfloat162_rn(make_float2(a, b));
    return *(uint32_t*)&h;
}

// ============================ kernel 1: split We ===========================
__global__ void splitw_kernel(const float* __restrict__ W) {
    int i = blockIdx.x * 256 + threadIdx.x;     // 65536 = A*E
    int a = i >> 8, e = i & 255;
    float w = W[a * 512 + 256 + e];             // We = W[:, 256:512]
    __nv_bfloat16 h = __float2bfloat16(w);
    float lo = w - __bfloat162float(h);
    ((__nv_bfloat16*)g_whe)[i] = h;
    ((__nv_bfloat16*)g_wle)[i] = __float2bfloat16(lo);
}

// ============================ kernel 2: proj ===============================
__global__ void proj_kernel(const float* __restrict__ dh, const float* __restrict__ W,
                            const float* __restrict__ bias) {
    int b = blockIdx.x, a = threadIdx.x;
    __shared__ float dsh[256];
    dsh[a] = dh[b * 256 + a];
    __syncthreads();
    const float4* wr = (const float4*)(W + a * 512);   // Wd row of thread's a
    float acc = bias[a];
#pragma unroll 8
    for (int d4 = 0; d4 < 64; d4++) {
        float4 w = wr[d4];
        acc += w.x * dsh[d4 * 4 + 0] + w.y * dsh[d4 * 4 + 1]
             + w.z * dsh[d4 * 4 + 2] + w.w * dsh[d4 * 4 + 3];
    }
    g_proj[b * 256 + a] = acc;
}

// ========== kernel 3: fused GEMM (HMMA bf16 3-split) + tanh + rowsum =======
// TILE_M=64, 2 CTAs/SM. smem: A_hi [64][256]bf16 swizzled, A_lo same,
// single We chunk buffer (hi 16KB + lo 16KB), score partials 512B.
// nsq partials overlay the We buffer (used before first prefetch).
#define OFF_AH   0
#define OFF_AL   32768
#define OFF_W    65536                  // 32768 bytes (hi 16384, lo +16384)
#define OFF_SC   98304                  // 128 floats (2 n-halves x 64 rows)
#define SMEM_P1  98816

__device__ __forceinline__ void prefetch_w(uint32_t sb, int chunk, int tid) {
    const int a0 = chunk * NCHUNK;
#pragma unroll
    for (int it = 0; it < 4; it++) {
        int idx = it * 256 + tid;               // 0..1023
        int n = idx >> 5, ck = idx & 31;
        uint32_t dst = (uint32_t)(n * 512 + ((ck ^ (n & 7)) << 4));
        cp16(sb + OFF_W + dst,         g_whe + (a0 + n) * 64 + ck * 2);
        cp16(sb + OFF_W + 16384 + dst, g_wle + (a0 + n) * 64 + ck * 2);
    }
    cp_commit();
}

__global__ void __launch_bounds__(256, 2) phase1_kernel(const float* __restrict__ eo) {
    extern __shared__ char smem[];
    const uint32_t sb  = smem_u32(smem);
    const int tid  = threadIdx.x;
    const int lane = tid & 31;
    const int w    = tid >> 5;
    const int r0   = blockIdx.x * TILE_M;

    float* nsq_part = (float*)(smem + OFF_W);     // [64][65] overlay (pre-MMA only)
    float* sc_part  = (float*)(smem + OFF_SC);    // [2][64]

    // ---- load eo tile (64 x 256 f32) -> bf16 hi/lo (swizzled), ssq partials
    {
        const float4* xg = (const float4*)eo;
        const int k4 = tid & 63;
        const int mb = tid >> 6;
#pragma unroll 4
        for (int it = 0; it < 16; it++) {
            int m = it * 4 + mb;
            float4 v = xg[(size_t)(r0 + m) * 64 + k4];
            uint32_t ph0 = packbf2f(v.x, v.y);
            uint32_t ph1 = packbf2f(v.z, v.w);
            uint32_t off = (uint32_t)(m * 512 + (((k4 >> 1) ^ (m & 7)) << 4) + ((k4 & 1) << 3));
            *(uint2*)(smem + OFF_AH + off) = make_uint2(ph0, ph1);
            float l0 = v.x - __uint_as_float(ph0 << 16);
            float l1 = v.y - __uint_as_float(ph0 & 0xffff0000u);
            float l2 = v.z - __uint_as_float(ph1 << 16);
            float l3 = v.w - __uint_as_float(ph1 & 0xffff0000u);
            *(uint2*)(smem + OFF_AL + off) = make_uint2(packbf2f(l0, l1), packbf2f(l2, l3));
            nsq_part[m * 65 + k4] = v.x * v.x + v.y * v.y + v.z * v.z + v.w * v.w;
        }
    }
    __syncthreads();

    // ---- norms: read partials into a register before We prefetch clobbers them
    float nsum = 0.f;
    if (tid < 64) {
        const float* p = nsq_part + tid * 65;
#pragma unroll
        for (int i = 0; i < 64; i++) nsum += p[i];
    }
    __syncthreads();               // all nsq reads done; We buffer now free

    prefetch_w(sb, 0, tid);        // chunk 0 in flight

    if (tid < 64) {
        int r = r0 + tid;
        g_normT[(r & 31) * S_SZ + (r >> 5)] = sqrtf(nsum);
    }

    // ---- per-warp fragment lane constants (warp = m16 x n16)
    const int mt = w & 3;                        // m-tile 0..3
    const int nh = w >> 2;                       // n-half 0..1 within n32 chunk
    const int t  = lane >> 3, rin = lane & 7;
    const int a_m     = mt * 16 + ((t & 1) << 3) + rin;
    const int a_khalf = t >> 1;
    const uint32_t a_base_h = sb + OFF_AH + (uint32_t)(a_m * 512);
    const uint32_t a_base_l = sb + OFF_AL + (uint32_t)(a_m * 512);
    const int a_sw = a_m & 7;
    const int b_n     = nh * 16 + ((t >> 1) << 3) + rin;   // 0..31
    const int b_khalf = t & 1;
    const int b_sw    = b_n & 7;
    const uint32_t b_base_h = sb + OFF_W + (uint32_t)(b_n * 512);
    const uint32_t b_base_l = b_base_h + 16384;

    const int rlo = mt * 16 + (lane >> 2);       // output row of acc[ ][0..1], 0..63
    const int qn  = (lane & 3) * 2;
    const float2* pl_base = (const float2*)(g_proj + (rlo & 31) * 256);
    const float2* ph_base = (const float2*)(g_proj + ((rlo + 8) & 31) * 256);

    float sum_lo = 0.f, sum_hi = 0.f;

    for (int c = 0; c < NCH; c++) {
        cp_wait0();
        __syncthreads();                  // We chunk c visible

        float acc[2][4];
#pragma unroll
        for (int j = 0; j < 2; j++)
#pragma unroll
            for (int q = 0; q < 4; q++) acc[j][q] = 0.f;

        // explicit 2-stage software pipeline of the 4 ldsm4 per k-step
        uint32_t ah[2][4], al[2][4], bh[2][4], bl[2][4];
        {
            uint32_t a_off = (uint32_t)((a_khalf ^ a_sw) << 4);
            uint32_t b_off = (uint32_t)((b_khalf ^ b_sw) << 4);
            ldsm4(ah[0], a_base_h + a_off);
            ldsm4(al[0], a_base_l + a_off);
            ldsm4(bh[0], b_base_h + b_off);
            ldsm4(bl[0], b_base_l + b_off);
        }
#pragma unroll
        for (int ks = 0; ks < 16; ks++) {
            const int cur = ks & 1, nxt = cur ^ 1;
            if (ks < 15) {
                int ck = (ks + 1) * 2;
                uint32_t a_off = (uint32_t)(((ck + a_khalf) ^ a_sw) << 4);
                uint32_t b_off = (uint32_t)(((ck + b_khalf) ^ b_sw) << 4);
                ldsm4(ah[nxt], a_base_h + a_off);
                ldsm4(al[nxt], a_base_l + a_off);
                ldsm4(bh[nxt], b_base_h + b_off);
                ldsm4(bl[nxt], b_base_l + b_off);
            }
            // hi*hi
            mma16816(acc[0], ah[cur], bh[cur][0], bh[cur][1]);
            mma16816(acc[1], ah[cur], bh[cur][2], bh[cur][3]);
            // hi*lo
            mma16816(acc[0], ah[cur], bl[cur][0], bl[cur][1]);
            mma16816(acc[1], ah[cur], bl[cur][2], bl[cur][3]);
            // lo*hi
            mma16816(acc[0], al[cur], bh[cur][0], bh[cur][1]);
            mma16816(acc[1], al[cur], bh[cur][2], bh[cur][3]);
        }
        __syncthreads();                  // all warps done reading We chunk c

        // prefetch next chunk; its latency overlaps the tanh epilogue below
        if (c + 1 < NCH) prefetch_w(sb, c + 1, tid);

        // ---- tanh epilogue for this chunk (this warp's 16 a-columns)
#pragma unroll
        for (int j = 0; j < 2; j++) {
            int nb2 = (c * NCHUNK + nh * 16 + j * 8 + qn) >> 1;   // float2 index
            float2 pl = __ldg(pl_base + nb2);
            float2 ph = __ldg(ph_base + nb2);
            sum_lo += tanh_fast(acc[j][0] + pl.x) + tanh_fast(acc[j][1] + pl.y);
            sum_hi += tanh_fast(acc[j][2] + ph.x) + tanh_fast(acc[j][3] + ph.y);
        }
    }

    // ---- reduce 4 lanes per row, combine the two n-half warps via smem
    sum_lo += __shfl_xor_sync(0xffffffffu, sum_lo, 1);
    sum_lo += __shfl_xor_sync(0xffffffffu, sum_lo, 2);
    sum_hi += __shfl_xor_sync(0xffffffffu, sum_hi, 1);
    sum_hi += __shfl_xor_sync(0xffffffffu, sum_hi, 2);
    if ((lane & 3) == 0) {
        sc_part[nh * 64 + rlo]     = sum_lo;
        sc_part[nh * 64 + rlo + 8] = sum_hi;
    }
    __syncthreads();
    if (tid < 64) {
        int r = r0 + tid;
        g_scoresT[(r & 31) * S_SZ + (r >> 5)] = sc_part[tid] + sc_part[64 + tid];
    }
}

// ============================ kernel 4: softmax stats ======================
__global__ void stats_kernel() {
    int b = blockIdx.x, t = threadIdx.x;
    __shared__ float red[256];
    const float* sc = g_scoresT + b * S_SZ;
    float m = -1e30f;
#pragma unroll 4
    for (int s = t; s < S_SZ; s += 256) m = fmaxf(m, sc[s]);
    red[t] = m; __syncthreads();
    for (int o = 128; o; o >>= 1) { if (t < o) red[t] = fmaxf(red[t], red[t + o]); __syncthreads(); }
    float smax = red[0]; __syncthreads();
    float sum = 0.f;
#pragma unroll 4
    for (int s = t; s < S_SZ; s += 256) sum += __expf(sc[s] - smax);
    red[t] = sum; __syncthreads();
    for (int o = 128; o; o >>= 1) { if (t < o) red[t] += red[t + o]; __syncthreads(); }
    if (t == 0) { g_smax[b] = smax; g_sinv[b] = 1.f / red[0]; }
}

// ======= kernel 5: weights, attn_map, attended partial sums ================
__global__ void attn_kernel(const float* __restrict__ eo, float* __restrict__ out) {
    int sc = blockIdx.x, b = blockIdx.y, t = threadIdx.x;
    __shared__ float wsm[256];
    float smax = g_smax[b], sinv = g_sinv[b];
    int s0 = sc * 256;
    int s = s0 + t;
    float wgt = __expf(g_scoresT[b * S_SZ + s] - smax) * sinv;
    wsm[t] = wgt;
    out[8192 + b * S_SZ + s] = wgt * g_normT[b * S_SZ + s];   // attn_map[b][s]
    __syncthreads();
    const float* base = eo + (size_t)s0 * (B_SZ * E_SZ) + b * E_SZ + t;
    float acc = 0.f;
#pragma unroll 16
    for (int s2 = 0; s2 < 256; s2++)
        acc = fmaf(wsm[s2], base[(size_t)s2 * (B_SZ * E_SZ)], acc);
    g_attpart[(b * NSC + sc) * E_SZ + t] = acc;
}

// ============================ kernel 6: final reduce =======================
__global__ void reduce_kernel(float* __restrict__ out) {
    int b = blockIdx.x, t = threadIdx.x;
    float a = 0.f;
#pragma unroll
    for (int sc = 0; sc < NSC; sc++) a += g_attpart[(b * NSC + sc) * E_SZ + t];
    out[b * E_SZ + t] = a;   // attended[b][e]
}

// ============================ launcher =====================================
extern "C" void kernel_launch(void* const* d_in, const int* in_sizes, int n_in,
                              void* d_out, int out_size) {
    const float* dh   = (const float*)d_in[0];  // (1,B,D)
    const float* eo   = (const float*)d_in[1];  // (S,B,E)
    const float* W    = (const float*)d_in[2];  // (A, D+E)
    const float* bias = (const float*)d_in[3];  // (A,)
    float* out = (float*)d_out;                 // [attended(32x256) | attn_map(32x4096)]

    cudaFuncSetAttribute(phase1_kernel, cudaFuncAttributeMaxDynamicSharedMemorySize, SMEM_P1);

    splitw_kernel<<<256, 256>>>(W);
    proj_kernel<<<32, 256>>>(dh, W, bias);
    phase1_kernel<<<NTILES, 256, SMEM_P1>>>(eo);
    stats_kernel<<<32, 256>>>();
    attn_kernel<<<dim3(NSC, 32), 256>>>(eo, out);
    reduce_kernel<<<32, 256>>>(out);
}